// round 4
// baseline (speedup 1.0000x reference)
#include <cuda_runtime.h>
#include <cstring>

// ---------------------------------------------------------------------------
// HyperEConv:
//   stream B: CSR build (hist -> offsets -> place), no memset (end-zero invariant)
//   stream A: xv = x@Wx1^T+bx1 ; wv = w@Ww1^T+bw1 ; we = w@Ww2^T+bw2
//   sr1: x_new = xv * (1 + segsum_v(wv[eidx]))
//   sr2: s     = segsum_e(x_new[vidx])
//   final: w_new = we * (1 + s@Wx2^T + deg_w*bx2)
// Output: [w_new (N_W*128) | x_new (N_X*128)]  float32
// ---------------------------------------------------------------------------

#define MAX_NX 100000
#define MAX_NW 25000
#define MAX_E  800000
#define D 128

__device__ float g_xv [MAX_NX * D];
__device__ float g_wv [MAX_NW * D];
__device__ float g_we [MAX_NW * D];
__device__ float g_s  [MAX_NW * D];

// counts: x segs [0,NX), w segs [NX,NX+NW), 2 counters at tail.
// INVARIANT: g_cnt (incl. counters) is all-zero at entry of every run
// (static zero-init on first run; zeroed at end of each run thereafter).
__device__ int g_cnt [MAX_NX + MAX_NW + 2];
__device__ int g_beg [MAX_NX + MAX_NW];
__device__ int g_cur [MAX_NX + MAX_NW];
__device__ int g_srcx[MAX_E];
__device__ int g_srcw[MAX_E];

// packed f32x2 FMA (2x fp32 FMA throughput; only reachable via PTX)
__device__ __forceinline__ float2 ffma2(float2 a, float2 b, float2 c) {
    unsigned long long au, bu, cu, du;
    memcpy(&au, &a, 8); memcpy(&bu, &b, 8); memcpy(&cu, &c, 8);
    asm("fma.rn.f32x2 %0, %1, %2, %3;" : "=l"(du) : "l"(au), "l"(bu), "l"(cu));
    float2 d; memcpy(&d, &du, 8);
    return d;
}

// ---------------------------------------------------------------------------
// GEMM: v[M,128] = A[M,128] @ W^T + bias*deg (deg=1 if null)
//   out = mulSrc ? mulSrc*(1+v) : v
// ---------------------------------------------------------------------------
extern __shared__ float smem_dyn[];

__global__ void __launch_bounds__(256, 1)
gemm128_kernel(const float* __restrict__ A, const float* __restrict__ W,
               const float* __restrict__ bias, float* __restrict__ C, int M,
               const int* __restrict__ deg, const float* __restrict__ mulSrc)
{
    float* Ast = smem_dyn;             // [k][row]
    float* Wt  = smem_dyn + 128 * 128; // [k][col]

    const int t  = threadIdx.x;
    const int tx = t & 15;
    const int ty = t >> 4;
    const int rowBase = blockIdx.x * 128;

    {
        const int r  = t >> 1;
        const int kh = (t & 1) * 64;
        const int grow = rowBase + r;
        const bool valid = grow < M;
        const float4* Ag = (const float4*)(A + (size_t)grow * D + kh);
        const float4* Wg = (const float4*)(W + (size_t)r * D + kh);
        #pragma unroll
        for (int q = 0; q < 16; q++) {
            float4 va = valid ? Ag[q] : make_float4(0.f, 0.f, 0.f, 0.f);
            int k0 = kh + q * 4;
            Ast[(k0 + 0) * 128 + r] = va.x;
            Ast[(k0 + 1) * 128 + r] = va.y;
            Ast[(k0 + 2) * 128 + r] = va.z;
            Ast[(k0 + 3) * 128 + r] = va.w;
            float4 vw = Wg[q];
            Wt[(k0 + 0) * 128 + r] = vw.x;
            Wt[(k0 + 1) * 128 + r] = vw.y;
            Wt[(k0 + 2) * 128 + r] = vw.z;
            Wt[(k0 + 3) * 128 + r] = vw.w;
        }
    }
    __syncthreads();

    float2 acc[4][8];
    #pragma unroll
    for (int i = 0; i < 4; i++)
        #pragma unroll
        for (int p = 0; p < 8; p++) acc[i][p] = make_float2(0.f, 0.f);

    #pragma unroll 4
    for (int k = 0; k < 128; k++) {
        float2 a2[4];
        #pragma unroll
        for (int i = 0; i < 4; i++)
            a2[i] = *(const float2*)&Ast[k * 128 + ty * 8 + 2 * i];
        #pragma unroll
        for (int p = 0; p < 8; p++) {
            float wv_ = Wt[k * 128 + tx + 16 * p];
            float2 w2 = make_float2(wv_, wv_);
            #pragma unroll
            for (int i = 0; i < 4; i++)
                acc[i][p] = ffma2(a2[i], w2, acc[i][p]);
        }
    }

    float b[8];
    #pragma unroll
    for (int p = 0; p < 8; p++) b[p] = bias[tx + 16 * p];

    const bool hasMul = (mulSrc != nullptr);

    #pragma unroll
    for (int i = 0; i < 4; i++) {
        int r0 = rowBase + ty * 8 + 2 * i;
        float d0 = 1.f, d1 = 1.f;
        if (deg != nullptr) {
            if (r0 < M)     d0 = (float)deg[r0];
            if (r0 + 1 < M) d1 = (float)deg[r0 + 1];
        }
        #pragma unroll
        for (int p = 0; p < 8; p++) {
            int col = tx + 16 * p;
            if (r0 < M) {
                float v = acc[i][p].x + b[p] * d0;
                if (hasMul) { float m = mulSrc[(size_t)r0 * D + col]; v = fmaf(m, v, m); }
                C[(size_t)r0 * D + col] = v;
            }
            if (r0 + 1 < M) {
                float v = acc[i][p].y + b[p] * d1;
                if (hasMul) { float m = mulSrc[(size_t)(r0 + 1) * D + col]; v = fmaf(m, v, m); }
                C[(size_t)(r0 + 1) * D + col] = v;
            }
        }
    }
}

// ---------------------------------------------------------------------------
// CSR build
// ---------------------------------------------------------------------------
__global__ void hist_kernel(const int* __restrict__ vidx, const int* __restrict__ eidx,
                            int* __restrict__ cnt, int nx, int E)
{
    int e = blockIdx.x * blockDim.x + threadIdx.x;
    if (e < E) {
        atomicAdd(&cnt[vidx[e]], 1);        // result unused -> REDG
        atomicAdd(&cnt[nx + eidx[e]], 1);
    }
}

// per-block scan + atomic base grab (unordered segment placement)
__global__ void __launch_bounds__(1024)
offsets_kernel(const int* __restrict__ cnt, int* __restrict__ beg,
               int* __restrict__ cur, int* __restrict__ ctr,
               int nx, int nw, int nbx)
{
    const int isW = (blockIdx.x >= nbx) ? 1 : 0;
    const int blk = isW ? (blockIdx.x - nbx) : blockIdx.x;
    const int n   = isW ? nw : nx;
    const int off = isW ? nx : 0;

    const int t = threadIdx.x;
    const int i = blk * 1024 + t;
    int v = (i < n) ? cnt[off + i] : 0;

    const int lane = t & 31, wid = t >> 5;
    int s = v;
    #pragma unroll
    for (int o = 1; o < 32; o <<= 1) {
        int u = __shfl_up_sync(0xffffffffu, s, o);
        if (lane >= o) s += u;
    }
    __shared__ int wsum[32];
    __shared__ int base;
    if (lane == 31) wsum[wid] = s;
    __syncthreads();
    if (wid == 0) {
        int ws = wsum[lane];
        #pragma unroll
        for (int o = 1; o < 32; o <<= 1) {
            int u = __shfl_up_sync(0xffffffffu, ws, o);
            if (lane >= o) ws += u;
        }
        wsum[lane] = ws;
        if (lane == 31) base = atomicAdd(&ctr[isW], ws);
    }
    __syncthreads();
    int excl = base + s - v + (wid > 0 ? wsum[wid - 1] : 0);
    if (i < n) { beg[off + i] = excl; cur[off + i] = excl; }
}

__global__ void place_kernel(const int* __restrict__ vidx, const int* __restrict__ eidx,
                             int* __restrict__ cur, int* __restrict__ srcx,
                             int* __restrict__ srcw, int nx, int E)
{
    int e = blockIdx.x * blockDim.x + threadIdx.x;
    if (e < E) {
        int v = vidx[e], hw = eidx[e];
        int p1 = atomicAdd(&cur[v], 1);
        srcx[p1] = hw;
        int p2 = atomicAdd(&cur[nx + hw], 1);
        srcw[p2] = v;
    }
}

__global__ void zero_kernel(int* __restrict__ p, int n)
{
    int i = blockIdx.x * blockDim.x + threadIdx.x;
    if (i < n) p[i] = 0;
}

// ---------------------------------------------------------------------------
// Segment gather-reduce: warp per segment; lane = float4 chunk. 8-deep MLP.
//   acc = sum_{k in [beg, beg+cnt)} src[lst[k]] ;  out = lin ? lin*(1+acc) : acc
// ---------------------------------------------------------------------------
__global__ void seg_reduce_kernel(const int* __restrict__ beg, const int* __restrict__ cnt,
                                  const int* __restrict__ lst,
                                  const float* __restrict__ src, const float* __restrict__ lin,
                                  float* __restrict__ out, int N)
{
    const int seg  = (blockIdx.x * blockDim.x + threadIdx.x) >> 5;
    const int lane = threadIdx.x & 31;
    if (seg >= N) return;
    int k = beg[seg];
    const int end = k + cnt[seg];
    const int j = lane * 4;
    float4 acc = make_float4(0.f, 0.f, 0.f, 0.f);

    for (; k + 7 < end; k += 8) {
        int  si[8];
        #pragma unroll
        for (int q = 0; q < 8; q++) si[q] = __ldg(&lst[k + q]);
        float4 v[8];
        #pragma unroll
        for (int q = 0; q < 8; q++)
            v[q] = *(const float4*)(src + (size_t)si[q] * D + j);
        #pragma unroll
        for (int q = 0; q < 8; q++) {
            acc.x += v[q].x; acc.y += v[q].y; acc.z += v[q].z; acc.w += v[q].w;
        }
    }
    if (k + 3 < end) {
        int  si[4];
        #pragma unroll
        for (int q = 0; q < 4; q++) si[q] = __ldg(&lst[k + q]);
        float4 v[4];
        #pragma unroll
        for (int q = 0; q < 4; q++)
            v[q] = *(const float4*)(src + (size_t)si[q] * D + j);
        #pragma unroll
        for (int q = 0; q < 4; q++) {
            acc.x += v[q].x; acc.y += v[q].y; acc.z += v[q].z; acc.w += v[q].w;
        }
        k += 4;
    }
    for (; k < end; k++) {
        int s0 = __ldg(&lst[k]);
        float4 v0 = *(const float4*)(src + (size_t)s0 * D + j);
        acc.x += v0.x; acc.y += v0.y; acc.z += v0.z; acc.w += v0.w;
    }

    float4 o;
    if (lin != nullptr) {
        float4 l = *(const float4*)(lin + (size_t)seg * D + j);
        o.x = fmaf(acc.x, l.x, l.x);
        o.y = fmaf(acc.y, l.y, l.y);
        o.z = fmaf(acc.z, l.z, l.z);
        o.w = fmaf(acc.w, l.w, l.w);
    } else {
        o = acc;
    }
    *(float4*)(out + (size_t)seg * D + j) = o;
}

extern "C" void kernel_launch(void* const* d_in, const int* in_sizes, int n_in,
                              void* d_out, int out_size)
{
    const float* x   = (const float*)d_in[0];
    const float* w   = (const float*)d_in[1];
    const float* Wx1 = (const float*)d_in[2];
    const float* bx1 = (const float*)d_in[3];
    const float* Ww1 = (const float*)d_in[4];
    const float* bw1 = (const float*)d_in[5];
    const float* Wx2 = (const float*)d_in[6];
    const float* bx2 = (const float*)d_in[7];
    const float* Ww2 = (const float*)d_in[8];
    const float* bw2 = (const float*)d_in[9];
    const int*   h   = (const int*)d_in[10];

    const int N_X = in_sizes[0] / D;
    const int N_W = in_sizes[1] / D;
    const int E   = in_sizes[10] / 2;
    const int* vidx = h;
    const int* eidx = h + E;

    float* out_w = (float*)d_out;
    float* out_x = (float*)d_out + (size_t)N_W * D;

    float *p_xv, *p_wv, *p_we, *p_s;
    int *p_cnt, *p_beg, *p_cur, *p_srcx, *p_srcw;
    cudaGetSymbolAddress((void**)&p_xv,   g_xv);
    cudaGetSymbolAddress((void**)&p_wv,   g_wv);
    cudaGetSymbolAddress((void**)&p_we,   g_we);
    cudaGetSymbolAddress((void**)&p_s,    g_s);
    cudaGetSymbolAddress((void**)&p_cnt,  g_cnt);
    cudaGetSymbolAddress((void**)&p_beg,  g_beg);
    cudaGetSymbolAddress((void**)&p_cur,  g_cur);
    cudaGetSymbolAddress((void**)&p_srcx, g_srcx);
    cudaGetSymbolAddress((void**)&p_srcw, g_srcw);
    int* p_ctr = p_cnt + MAX_NX + MAX_NW;

    const int SMEM = 2 * 128 * 128 * (int)sizeof(float); // 128 KB
    cudaFuncSetAttribute(gemm128_kernel,
                         cudaFuncAttributeMaxDynamicSharedMemorySize, SMEM);

    static cudaStream_t sA = nullptr, sB = nullptr;
    static cudaEvent_t e0 = nullptr, eA = nullptr, eA2 = nullptr, eB = nullptr, eS1 = nullptr;
    if (sA == nullptr) {
        cudaStreamCreateWithFlags(&sA, cudaStreamNonBlocking);
        cudaStreamCreateWithFlags(&sB, cudaStreamNonBlocking);
        cudaEventCreateWithFlags(&e0,  cudaEventDisableTiming);
        cudaEventCreateWithFlags(&eA,  cudaEventDisableTiming);
        cudaEventCreateWithFlags(&eA2, cudaEventDisableTiming);
        cudaEventCreateWithFlags(&eB,  cudaEventDisableTiming);
        cudaEventCreateWithFlags(&eS1, cudaEventDisableTiming);
    }

    const int gx  = (N_X + 127) / 128;
    const int gw  = (N_W + 127) / 128;
    const int nbx = (N_X + 1023) / 1024;
    const int nbw = (N_W + 1023) / 1024;
    const int ge  = (E + 255) / 256;

    // fork
    cudaEventRecord(e0, 0);
    cudaStreamWaitEvent(sA, e0, 0);
    cudaStreamWaitEvent(sB, e0, 0);

    // ---- stream B: CSR (launches 1-3). cnt is all-zero on entry (invariant). ----
    hist_kernel<<<ge, 256, 0, sB>>>(vidx, eidx, p_cnt, N_X, E);
    offsets_kernel<<<nbx + nbw, 1024, 0, sB>>>(p_cnt, p_beg, p_cur, p_ctr, N_X, N_W, nbx);
    place_kernel<<<ge, 256, 0, sB>>>(vidx, eidx, p_cur, p_srcx, p_srcw, N_X, E);
    cudaEventRecord(eB, sB);

    // ---- stream A: GEMMs (launches 4-5) ----
    gemm128_kernel<<<gw, 256, SMEM, sA>>>(w, Ww1, bw1, p_wv, N_W, nullptr, nullptr);
    gemm128_kernel<<<gx, 256, SMEM, sA>>>(x, Wx1, bx1, p_xv, N_X, nullptr, nullptr);
    cudaEventRecord(eA, sA);

    // join for phase 1
    cudaStreamWaitEvent(0, eA, 0);
    cudaStreamWaitEvent(0, eB, 0);

    // ---- launch 6 (PROFILED): sr1: x_new = xv * (1 + segsum_v(wv)) ----
    seg_reduce_kernel<<<(N_X + 7) / 8, 256>>>(p_beg, p_cnt, p_srcx, p_wv, p_xv, out_x, N_X);
    cudaEventRecord(eS1, 0);

    // ---- launch 7: we-GEMM on stream A (executes concurrently with sr1) ----
    gemm128_kernel<<<gw, 256, SMEM, sA>>>(w, Ww2, bw2, p_we, N_W, nullptr, nullptr);
    cudaEventRecord(eA2, sA);

    // ---- launch 8: re-zero x-part of cnt on stream B (after sr1 consumed it) ----
    cudaStreamWaitEvent(sB, eS1, 0);
    zero_kernel<<<(N_X + 255) / 256, 256, 0, sB>>>(p_cnt, N_X);
    cudaEventRecord(eB, sB);

    // ---- phase 2: s = segsum_e(x_new); w_new = we*(1 + s@Wx2^T + deg*bx2) ----
    seg_reduce_kernel<<<(N_W + 7) / 8, 256>>>(p_beg + N_X, p_cnt + N_X, p_srcw,
                                              out_x, nullptr, p_s, N_W);
    cudaStreamWaitEvent(0, eA2, 0);
    gemm128_kernel<<<gw, 256, SMEM>>>(p_s, Wx2, bx2, out_w, N_W, p_cnt + N_X, p_we);

    // ---- tail: restore zero-invariant for w-part of cnt + counters ----
    zero_kernel<<<(N_W + 2 + 255) / 256, 256>>>(p_cnt + N_X, N_W + 2);
    cudaStreamWaitEvent(0, eB, 0);   // ensure x-part zeroing is inside the graph's deps
}

// round 6
// speedup vs baseline: 1.3552x; 1.3552x over previous
#include <cuda_runtime.h>
#include <cuda_bf16.h>
#include <cstring>
#include <cstdint>

// ---------------------------------------------------------------------------
// HyperEConv with mma.sync (HMMA) bf16-split GEMMs (family-safe PTX):
//   stream B: CSR build (hist -> offsets -> place)
//   stream A: xv = x@Wx1^T+bx1 ; wv = w@Ww1^T+bw1 ; we = w@Ww2^T+bw2
//   sr1: x_new = xv * (1 + segsum_v(wv[eidx]))
//   sr2: s     = segsum_e(x_new[vidx])
//   final: w_new = we * (1 + s@Wx2^T + deg_w*bx2)
// GEMM: D = Ahi*Bhi + Ahi*Blo + Alo*Bhi  (bf16 in, fp32 accum)
// Output: [w_new (N_W*128) | x_new (N_X*128)]  float32
// ---------------------------------------------------------------------------

#define MAX_NX 100000
#define MAX_NW 25000
#define MAX_E  800000
#define D 128

__device__ float g_xv [MAX_NX * D];
__device__ float g_wv [MAX_NW * D];
__device__ float g_we [MAX_NW * D];
__device__ float g_s  [MAX_NW * D];

// counts: x segs [0,NX), w segs [NX,NX+NW), 2 counters at tail.
// INVARIANT: all-zero at entry of every run (zeroed at end of each run).
__device__ int g_cnt [MAX_NX + MAX_NW + 2];
__device__ int g_beg [MAX_NX + MAX_NW];
__device__ int g_cur [MAX_NX + MAX_NW];
__device__ int g_srcx[MAX_E];
__device__ int g_srcw[MAX_E];

__device__ __forceinline__ uint32_t smem_u32(const void* p) {
    uint32_t a;
    asm("{ .reg .u64 t; cvta.to.shared.u64 t, %1; cvt.u32.u64 %0, t; }"
        : "=r"(a) : "l"(p));
    return a;
}

__device__ __forceinline__ void ldmx4(uint32_t* r, uint32_t addr) {
    asm volatile("ldmatrix.sync.aligned.m8n8.x4.shared.b16 {%0,%1,%2,%3}, [%4];"
                 : "=r"(r[0]), "=r"(r[1]), "=r"(r[2]), "=r"(r[3]) : "r"(addr));
}

__device__ __forceinline__ void mma_bf16(float* d, const uint32_t* a,
                                         uint32_t b0, uint32_t b1) {
    asm volatile(
        "mma.sync.aligned.m16n8k16.row.col.f32.bf16.bf16.f32 "
        "{%0,%1,%2,%3}, {%4,%5,%6,%7}, {%8,%9}, {%0,%1,%2,%3};"
        : "+f"(d[0]), "+f"(d[1]), "+f"(d[2]), "+f"(d[3])
        : "r"(a[0]), "r"(a[1]), "r"(a[2]), "r"(a[3]), "r"(b0), "r"(b1));
}

// split a pair of fp32 into bf16 hi/lo packed words
__device__ __forceinline__ void split2(float f0, float f1, uint32_t& hi, uint32_t& lo) {
    __nv_bfloat162 hh = __floats2bfloat162_rn(f0, f1);
    float r0 = f0 - __bfloat162float(hh.x);
    float r1 = f1 - __bfloat162float(hh.y);
    __nv_bfloat162 ll = __floats2bfloat162_rn(r0, r1);
    memcpy(&hi, &hh, 4);
    memcpy(&lo, &ll, 4);
}

// smem: 4 buffers of [128 rows][128 bf16] = 32KB each; 16B chunks, chunk
// swizzle c' = c ^ (row & 7)  -> conflict-free ldmatrix
#define SM_AHI  0
#define SM_ALO  32768
#define SM_BHI  65536
#define SM_BLO  98304
#define SM_TOT  131072

// ---------------------------------------------------------------------------
// HMMA GEMM: C[M,128] = A[M,128] @ W^T + bias*deg (deg=1 if null)
//   out = mulSrc ? mulSrc*(1+v) : v
// 256 threads, 128-row tile per block, warps in 4(m) x 2(n) grid.
// ---------------------------------------------------------------------------
extern __shared__ char smc[];

__global__ void __launch_bounds__(256, 1)
gemm_hmma_kernel(const float* __restrict__ A, const float* __restrict__ W,
                 const float* __restrict__ bias, float* __restrict__ C, int M,
                 const int* __restrict__ deg, const float* __restrict__ mulSrc)
{
    const uint32_t sb = smem_u32(smc);
    const int tid = threadIdx.x;
    const int rowBase = blockIdx.x * 128;

    // ---- convert A tile and W to bf16 hi/lo in swizzled smem ----
    {
        const int r  = tid >> 1;           // 0..127
        const int kh = (tid & 1) * 64;     // k half
        const int grow = rowBase + r;
        const bool valid = grow < M;
        const float4* Ag = (const float4*)(A + (size_t)grow * D + kh);
        const float4* Wg = (const float4*)(W + (size_t)r * D + kh);
        #pragma unroll
        for (int g = 0; g < 8; g++) {
            const int c = (kh >> 3) + g;                    // chunk index 0..15
            const uint32_t off = (uint32_t)r * 256u + (uint32_t)((c ^ (r & 7)) << 4);
            // A
            float4 u = valid ? Ag[2 * g]     : make_float4(0.f, 0.f, 0.f, 0.f);
            float4 v = valid ? Ag[2 * g + 1] : make_float4(0.f, 0.f, 0.f, 0.f);
            uint4 hi, lo;
            split2(u.x, u.y, hi.x, lo.x);
            split2(u.z, u.w, hi.y, lo.y);
            split2(v.x, v.y, hi.z, lo.z);
            split2(v.z, v.w, hi.w, lo.w);
            *(uint4*)(smc + SM_AHI + off) = hi;
            *(uint4*)(smc + SM_ALO + off) = lo;
            // W
            float4 wu = Wg[2 * g];
            float4 wv2 = Wg[2 * g + 1];
            split2(wu.x, wu.y, hi.x, lo.x);
            split2(wu.z, wu.w, hi.y, lo.y);
            split2(wv2.x, wv2.y, hi.z, lo.z);
            split2(wv2.z, wv2.w, hi.w, lo.w);
            *(uint4*)(smc + SM_BHI + off) = hi;
            *(uint4*)(smc + SM_BLO + off) = lo;
        }
    }
    __syncthreads();

    // ---- warp tiling: wm in 0..3 (32 rows), wn in 0..1 (64 cols) ----
    const int lane = tid & 31;
    const int wid  = tid >> 5;
    const int wm = wid & 3;
    const int wn = wid >> 2;
    const int m0  = wm * 32;
    const int n0w = wn * 64;
    const int sub = lane >> 3, l8 = lane & 7;

    float acc[2][8][4];
    #pragma unroll
    for (int at = 0; at < 2; at++)
        #pragma unroll
        for (int nt = 0; nt < 8; nt++)
            #pragma unroll
            for (int q = 0; q < 4; q++) acc[at][nt][q] = 0.f;

    for (int ks = 0; ks < 8; ks++) {
        uint32_t ahi[2][4], alo[2][4], bhi[4][4], blo[4][4];
        #pragma unroll
        for (int at = 0; at < 2; at++) {
            const int ar  = m0 + at * 16 + (sub & 1) * 8 + l8;
            const int akc = ks * 2 + (sub >> 1);
            const uint32_t aoff = (uint32_t)ar * 256u + (uint32_t)((akc ^ (ar & 7)) << 4);
            ldmx4(ahi[at], sb + SM_AHI + aoff);
            ldmx4(alo[at], sb + SM_ALO + aoff);
        }
        #pragma unroll
        for (int bp = 0; bp < 4; bp++) {
            const int br  = n0w + bp * 16 + (sub >> 1) * 8 + l8;
            const int bkc = ks * 2 + (sub & 1);
            const uint32_t boff = (uint32_t)br * 256u + (uint32_t)((bkc ^ (br & 7)) << 4);
            ldmx4(bhi[bp], sb + SM_BHI + boff);
            ldmx4(blo[bp], sb + SM_BLO + boff);
        }
        #pragma unroll
        for (int at = 0; at < 2; at++) {
            #pragma unroll
            for (int nt = 0; nt < 8; nt++) {
                const int bp = nt >> 1, o = (nt & 1) * 2;
                mma_bf16(acc[at][nt], ahi[at], bhi[bp][o], bhi[bp][o + 1]);
                mma_bf16(acc[at][nt], ahi[at], blo[bp][o], blo[bp][o + 1]);
                mma_bf16(acc[at][nt], alo[at], bhi[bp][o], bhi[bp][o + 1]);
            }
        }
    }

    // ---- epilogue: d0,d1 -> (row, col..col+1); d2,d3 -> (row+8, col..col+1) ----
    const bool hasMul = (mulSrc != nullptr);
    #pragma unroll
    for (int at = 0; at < 2; at++) {
        const int rloc = m0 + at * 16 + (lane >> 2);
        const int rA = rowBase + rloc;      // row for d0,d1
        const int rB = rA + 8;              // row for d2,d3
        float dA = 1.f, dB = 1.f;
        if (deg != nullptr) {
            if (rA < M) dA = (float)deg[rA];
            if (rB < M) dB = (float)deg[rB];
        }
        #pragma unroll
        for (int nt = 0; nt < 8; nt++) {
            const int col = n0w + nt * 8 + (lane & 3) * 2;
            const float2 b2 = *(const float2*)(bias + col);
            if (rA < M) {
                float v0 = acc[at][nt][0] + b2.x * dA;
                float v1 = acc[at][nt][1] + b2.y * dA;
                if (hasMul) {
                    float2 m = *(const float2*)(mulSrc + (size_t)rA * D + col);
                    v0 = fmaf(m.x, v0, m.x);
                    v1 = fmaf(m.y, v1, m.y);
                }
                *(float2*)(C + (size_t)rA * D + col) = make_float2(v0, v1);
            }
            if (rB < M) {
                float v0 = acc[at][nt][2] + b2.x * dB;
                float v1 = acc[at][nt][3] + b2.y * dB;
                if (hasMul) {
                    float2 m = *(const float2*)(mulSrc + (size_t)rB * D + col);
                    v0 = fmaf(m.x, v0, m.x);
                    v1 = fmaf(m.y, v1, m.y);
                }
                *(float2*)(C + (size_t)rB * D + col) = make_float2(v0, v1);
            }
        }
    }
}

// ---------------------------------------------------------------------------
// CSR build
// ---------------------------------------------------------------------------
__global__ void hist_kernel(const int* __restrict__ vidx, const int* __restrict__ eidx,
                            int* __restrict__ cnt, int nx, int E)
{
    int e = blockIdx.x * blockDim.x + threadIdx.x;
    if (e < E) {
        atomicAdd(&cnt[vidx[e]], 1);
        atomicAdd(&cnt[nx + eidx[e]], 1);
    }
}

__global__ void __launch_bounds__(1024)
offsets_kernel(const int* __restrict__ cnt, int* __restrict__ beg,
               int* __restrict__ cur, int* __restrict__ ctr,
               int nx, int nw, int nbx)
{
    const int isW = (blockIdx.x >= nbx) ? 1 : 0;
    const int blk = isW ? (blockIdx.x - nbx) : blockIdx.x;
    const int n   = isW ? nw : nx;
    const int off = isW ? nx : 0;

    const int t = threadIdx.x;
    const int i = blk * 1024 + t;
    int v = (i < n) ? cnt[off + i] : 0;

    const int lane = t & 31, wd = t >> 5;
    int s = v;
    #pragma unroll
    for (int o = 1; o < 32; o <<= 1) {
        int u = __shfl_up_sync(0xffffffffu, s, o);
        if (lane >= o) s += u;
    }
    __shared__ int wsum[32];
    __shared__ int base;
    if (lane == 31) wsum[wd] = s;
    __syncthreads();
    if (wd == 0) {
        int ws = wsum[lane];
        #pragma unroll
        for (int o = 1; o < 32; o <<= 1) {
            int u = __shfl_up_sync(0xffffffffu, ws, o);
            if (lane >= o) ws += u;
        }
        wsum[lane] = ws;
        if (lane == 31) base = atomicAdd(&ctr[isW], ws);
    }
    __syncthreads();
    int excl = base + s - v + (wd > 0 ? wsum[wd - 1] : 0);
    if (i < n) { beg[off + i] = excl; cur[off + i] = excl; }
}

__global__ void place_kernel(const int* __restrict__ vidx, const int* __restrict__ eidx,
                             int* __restrict__ cur, int* __restrict__ srcx,
                             int* __restrict__ srcw, int nx, int E)
{
    int e = blockIdx.x * blockDim.x + threadIdx.x;
    if (e < E) {
        int v = vidx[e], hw = eidx[e];
        int p1 = atomicAdd(&cur[v], 1);
        srcx[p1] = hw;
        int p2 = atomicAdd(&cur[nx + hw], 1);
        srcw[p2] = v;
    }
}

__global__ void zero_kernel(int* __restrict__ p, int n)
{
    int i = blockIdx.x * blockDim.x + threadIdx.x;
    if (i < n) p[i] = 0;
}

// ---------------------------------------------------------------------------
// Segment gather-reduce: warp per segment; lane = float4 chunk. 8-deep MLP.
// ---------------------------------------------------------------------------
__global__ void seg_reduce_kernel(const int* __restrict__ beg, const int* __restrict__ cnt,
                                  const int* __restrict__ lst,
                                  const float* __restrict__ src, const float* __restrict__ lin,
                                  float* __restrict__ out, int N)
{
    const int seg  = (blockIdx.x * blockDim.x + threadIdx.x) >> 5;
    const int lane = threadIdx.x & 31;
    if (seg >= N) return;
    int k = beg[seg];
    const int end = k + cnt[seg];
    const int j = lane * 4;
    float4 acc = make_float4(0.f, 0.f, 0.f, 0.f);

    for (; k + 7 < end; k += 8) {
        int si[8];
        #pragma unroll
        for (int q = 0; q < 8; q++) si[q] = __ldg(&lst[k + q]);
        float4 v[8];
        #pragma unroll
        for (int q = 0; q < 8; q++)
            v[q] = *(const float4*)(src + (size_t)si[q] * D + j);
        #pragma unroll
        for (int q = 0; q < 8; q++) {
            acc.x += v[q].x; acc.y += v[q].y; acc.z += v[q].z; acc.w += v[q].w;
        }
    }
    if (k + 3 < end) {
        int si[4];
        #pragma unroll
        for (int q = 0; q < 4; q++) si[q] = __ldg(&lst[k + q]);
        float4 v[4];
        #pragma unroll
        for (int q = 0; q < 4; q++)
            v[q] = *(const float4*)(src + (size_t)si[q] * D + j);
        #pragma unroll
        for (int q = 0; q < 4; q++) {
            acc.x += v[q].x; acc.y += v[q].y; acc.z += v[q].z; acc.w += v[q].w;
        }
        k += 4;
    }
    for (; k < end; k++) {
        int s0 = __ldg(&lst[k]);
        float4 v0 = *(const float4*)(src + (size_t)s0 * D + j);
        acc.x += v0.x; acc.y += v0.y; acc.z += v0.z; acc.w += v0.w;
    }

    float4 o;
    if (lin != nullptr) {
        float4 l = *(const float4*)(lin + (size_t)seg * D + j);
        o.x = fmaf(acc.x, l.x, l.x);
        o.y = fmaf(acc.y, l.y, l.y);
        o.z = fmaf(acc.z, l.z, l.z);
        o.w = fmaf(acc.w, l.w, l.w);
    } else {
        o = acc;
    }
    *(float4*)(out + (size_t)seg * D + j) = o;
}

extern "C" void kernel_launch(void* const* d_in, const int* in_sizes, int n_in,
                              void* d_out, int out_size)
{
    const float* x   = (const float*)d_in[0];
    const float* w   = (const float*)d_in[1];
    const float* Wx1 = (const float*)d_in[2];
    const float* bx1 = (const float*)d_in[3];
    const float* Ww1 = (const float*)d_in[4];
    const float* bw1 = (const float*)d_in[5];
    const float* Wx2 = (const float*)d_in[6];
    const float* bx2 = (const float*)d_in[7];
    const float* Ww2 = (const float*)d_in[8];
    const float* bw2 = (const float*)d_in[9];
    const int*   h   = (const int*)d_in[10];

    const int N_X = in_sizes[0] / D;
    const int N_W = in_sizes[1] / D;
    const int E   = in_sizes[10] / 2;
    const int* vidx = h;
    const int* eidx = h + E;

    float* out_w = (float*)d_out;
    float* out_x = (float*)d_out + (size_t)N_W * D;

    float *p_xv, *p_wv, *p_we, *p_s;
    int *p_cnt, *p_beg, *p_cur, *p_srcx, *p_srcw;
    cudaGetSymbolAddress((void**)&p_xv,   g_xv);
    cudaGetSymbolAddress((void**)&p_wv,   g_wv);
    cudaGetSymbolAddress((void**)&p_we,   g_we);
    cudaGetSymbolAddress((void**)&p_s,    g_s);
    cudaGetSymbolAddress((void**)&p_cnt,  g_cnt);
    cudaGetSymbolAddress((void**)&p_beg,  g_beg);
    cudaGetSymbolAddress((void**)&p_cur,  g_cur);
    cudaGetSymbolAddress((void**)&p_srcx, g_srcx);
    cudaGetSymbolAddress((void**)&p_srcw, g_srcw);
    int* p_ctr = p_cnt + MAX_NX + MAX_NW;

    cudaFuncSetAttribute(gemm_hmma_kernel,
                         cudaFuncAttributeMaxDynamicSharedMemorySize, SM_TOT);

    static cudaStream_t sA = nullptr, sB = nullptr;
    static cudaEvent_t e0 = nullptr, eA = nullptr, eA2 = nullptr, eB = nullptr, eS1 = nullptr;
    if (sA == nullptr) {
        cudaStreamCreateWithFlags(&sA, cudaStreamNonBlocking);
        cudaStreamCreateWithFlags(&sB, cudaStreamNonBlocking);
        cudaEventCreateWithFlags(&e0,  cudaEventDisableTiming);
        cudaEventCreateWithFlags(&eA,  cudaEventDisableTiming);
        cudaEventCreateWithFlags(&eA2, cudaEventDisableTiming);
        cudaEventCreateWithFlags(&eB,  cudaEventDisableTiming);
        cudaEventCreateWithFlags(&eS1, cudaEventDisableTiming);
    }

    const int gx  = (N_X + 127) / 128;
    const int gw  = (N_W + 127) / 128;
    const int nbx = (N_X + 1023) / 1024;
    const int nbw = (N_W + 1023) / 1024;
    const int ge  = (E + 255) / 256;

    // fork
    cudaEventRecord(e0, 0);
    cudaStreamWaitEvent(sA, e0, 0);
    cudaStreamWaitEvent(sB, e0, 0);

    // ---- stream B: CSR build (cnt all-zero on entry by invariant) ----
    hist_kernel<<<ge, 256, 0, sB>>>(vidx, eidx, p_cnt, N_X, E);
    offsets_kernel<<<nbx + nbw, 1024, 0, sB>>>(p_cnt, p_beg, p_cur, p_ctr, N_X, N_W, nbx);
    place_kernel<<<ge, 256, 0, sB>>>(vidx, eidx, p_cur, p_srcx, p_srcw, N_X, E);
    cudaEventRecord(eB, sB);

    // ---- stream A: GEMMs (HMMA) ----
    gemm_hmma_kernel<<<gw, 256, SM_TOT, sA>>>(w, Ww1, bw1, p_wv, N_W, nullptr, nullptr);
    gemm_hmma_kernel<<<gx, 256, SM_TOT, sA>>>(x, Wx1, bx1, p_xv, N_X, nullptr, nullptr);
    cudaEventRecord(eA, sA);

    // join for phase 1
    cudaStreamWaitEvent(0, eA, 0);
    cudaStreamWaitEvent(0, eB, 0);

    // ---- sr1: x_new = xv * (1 + segsum_v(wv)) ----
    seg_reduce_kernel<<<(N_X + 7) / 8, 256>>>(p_beg, p_cnt, p_srcx, p_wv, p_xv, out_x, N_X);
    cudaEventRecord(eS1, 0);

    // ---- we-GEMM on stream A (overlaps sr1) ----
    gemm_hmma_kernel<<<gw, 256, SM_TOT, sA>>>(w, Ww2, bw2, p_we, N_W, nullptr, nullptr);
    cudaEventRecord(eA2, sA);

    // ---- re-zero x-part of cnt (after sr1 consumed it) on stream B ----
    cudaStreamWaitEvent(sB, eS1, 0);
    zero_kernel<<<(N_X + 255) / 256, 256, 0, sB>>>(p_cnt, N_X);
    cudaEventRecord(eB, sB);

    // ---- phase 2: s = segsum_e(x_new); w_new = we*(1 + s@Wx2^T + deg*bx2) ----
    seg_reduce_kernel<<<(N_W + 7) / 8, 256>>>(p_beg + N_X, p_cnt + N_X, p_srcw,
                                              out_x, nullptr, p_s, N_W);
    cudaStreamWaitEvent(0, eA2, 0);
    gemm_hmma_kernel<<<gw, 256, SM_TOT>>>(p_s, Wx2, bx2, out_w, N_W, p_cnt + N_X, p_we);

    // ---- tail: restore zero-invariant for w-part of cnt + counters ----
    zero_kernel<<<(N_W + 2 + 255) / 256, 256>>>(p_cnt + N_X, N_W + 2);
    cudaStreamWaitEvent(0, eB, 0);
}

// round 7
// speedup vs baseline: 1.7055x; 1.2585x over previous
#include <cuda_runtime.h>
#include <cuda_bf16.h>
#include <cstring>
#include <cstdint>

// ---------------------------------------------------------------------------
// HyperEConv, HMMA bf16-split GEMMs, 64-row tiles + precomputed bf16 weights:
//   conv_w: all 4 weight matrices -> swizzled bf16 hi/lo global buffers
//   stream B: CSR build (hist -> offsets -> place)
//   stream A: wv = w@Ww1^T+bw1 ; xv = x@Wx1^T+bx1 ; we = w@Ww2^T+bw2
//   sr1: x_new = xv * (1 + segsum_v(wv[eidx]))
//   sr2: s     = segsum_e(x_new[vidx])
//   final: w_new = we * (1 + s@Wx2^T + deg_w*bx2)
// GEMM: D = Ahi*Bhi + Ahi*Blo + Alo*Bhi  (bf16 in, fp32 accum)
// Output: [w_new (N_W*128) | x_new (N_X*128)]  float32
// ---------------------------------------------------------------------------

#define MAX_NX 100000
#define MAX_NW 25000
#define MAX_E  800000
#define D 128

__device__ float g_xv [MAX_NX * D];
__device__ float g_wv [MAX_NW * D];
__device__ float g_we [MAX_NW * D];
__device__ float g_s  [MAX_NW * D];

// precomputed bf16 weights: [mat][hi=0/lo=1][2048 uint4] in swizzled layout
__device__ uint4 g_wbf[4][2][2048];

// counts: x segs [0,NX), w segs [NX,NX+NW), 2 counters at tail.
// INVARIANT: all-zero at entry of every run (zeroed at end of each run).
__device__ int g_cnt [MAX_NX + MAX_NW + 2];
__device__ int g_beg [MAX_NX + MAX_NW];
__device__ int g_cur [MAX_NX + MAX_NW];
__device__ int g_srcx[MAX_E];
__device__ int g_srcw[MAX_E];

__device__ __forceinline__ uint32_t smem_u32(const void* p) {
    uint32_t a;
    asm("{ .reg .u64 t; cvta.to.shared.u64 t, %1; cvt.u32.u64 %0, t; }"
        : "=r"(a) : "l"(p));
    return a;
}

__device__ __forceinline__ void ldmx4(uint32_t* r, uint32_t addr) {
    asm volatile("ldmatrix.sync.aligned.m8n8.x4.shared.b16 {%0,%1,%2,%3}, [%4];"
                 : "=r"(r[0]), "=r"(r[1]), "=r"(r[2]), "=r"(r[3]) : "r"(addr));
}

__device__ __forceinline__ void mma_bf16(float* d, const uint32_t* a,
                                         uint32_t b0, uint32_t b1) {
    asm volatile(
        "mma.sync.aligned.m16n8k16.row.col.f32.bf16.bf16.f32 "
        "{%0,%1,%2,%3}, {%4,%5,%6,%7}, {%8,%9}, {%0,%1,%2,%3};"
        : "+f"(d[0]), "+f"(d[1]), "+f"(d[2]), "+f"(d[3])
        : "r"(a[0]), "r"(a[1]), "r"(a[2]), "r"(a[3]), "r"(b0), "r"(b1));
}

__device__ __forceinline__ void split2(float f0, float f1, uint32_t& hi, uint32_t& lo) {
    __nv_bfloat162 hh = __floats2bfloat162_rn(f0, f1);
    float r0 = f0 - __bfloat162float(hh.x);
    float r1 = f1 - __bfloat162float(hh.y);
    __nv_bfloat162 ll = __floats2bfloat162_rn(r0, r1);
    memcpy(&hi, &hh, 4);
    memcpy(&lo, &ll, 4);
}

// smem layout: A 64 rows x 256B (hi/lo = 16KB each), W 128 rows x 256B (hi/lo 32KB each)
#define SM_AHI  0
#define SM_ALO  16384
#define SM_BHI  32768
#define SM_BLO  65536
#define SM_TOT  98304

extern __shared__ char smc[];

// ---------------------------------------------------------------------------
// Weight precompute: convert 4 [128x128] fp32 matrices to swizzled bf16 hi/lo.
// 8192 chunk-tasks (mat, row, chunk); chunk = 8 consecutive cols (16B bf16).
// ---------------------------------------------------------------------------
__global__ void conv_w_kernel(const float* __restrict__ W0, const float* __restrict__ W1,
                              const float* __restrict__ W2, const float* __restrict__ W3)
{
    const int t = blockIdx.x * blockDim.x + threadIdx.x;
    if (t >= 8192) return;
    const int mat = t >> 11;
    const int rem = t & 2047;
    const int r = rem >> 4;
    const int c = rem & 15;
    const float* Wm = (mat == 0) ? W0 : (mat == 1) ? W1 : (mat == 2) ? W2 : W3;
    const float4 u = *(const float4*)(Wm + r * 128 + c * 8);
    const float4 v = *(const float4*)(Wm + r * 128 + c * 8 + 4);
    uint4 hi, lo;
    split2(u.x, u.y, hi.x, lo.x);
    split2(u.z, u.w, hi.y, lo.y);
    split2(v.x, v.y, hi.z, lo.z);
    split2(v.z, v.w, hi.w, lo.w);
    const int off = r * 16 + (c ^ (r & 7));
    g_wbf[mat][0][off] = hi;
    g_wbf[mat][1][off] = lo;
}

// ---------------------------------------------------------------------------
// HMMA GEMM: C[M,128] = A[M,128] @ W^T + bias*deg (deg=1 if null)
//   out = mulSrc ? mulSrc*(1+v) : v
// 256 threads, 64-row tile, warps 2(m) x 4(n). 96KB smem -> 2 CTAs/SM.
// ---------------------------------------------------------------------------
__global__ void __launch_bounds__(256, 2)
gemm_hmma_kernel(const float* __restrict__ A, int wmat,
                 const float* __restrict__ bias, float* __restrict__ C, int M,
                 const int* __restrict__ deg, const float* __restrict__ mulSrc)
{
    const uint32_t sb = smem_u32(smc);
    const int tid = threadIdx.x;
    const int rowBase = blockIdx.x * 64;

    // ---- copy precomputed W hi/lo (already swizzled) ----
    {
        const uint4* whi = g_wbf[wmat][0];
        const uint4* wlo = g_wbf[wmat][1];
        uint4* shi = (uint4*)(smc + SM_BHI);
        uint4* slo = (uint4*)(smc + SM_BLO);
        #pragma unroll
        for (int it = 0; it < 8; it++) {
            const int i = tid + it * 256;
            shi[i] = whi[i];
            slo[i] = wlo[i];
        }
    }

    // ---- convert A tile (64 rows) to bf16 hi/lo swizzled smem ----
    {
        #pragma unroll
        for (int it = 0; it < 4; it++) {
            const int task = tid + it * 256;         // 0..1023
            const int r = task >> 4;
            const int c = task & 15;
            const int grow = rowBase + r;
            float4 u = make_float4(0.f, 0.f, 0.f, 0.f), v = u;
            if (grow < M) {
                const float* Ar = A + (size_t)grow * D + c * 8;
                u = *(const float4*)Ar;
                v = *(const float4*)(Ar + 4);
            }
            uint4 hi, lo;
            split2(u.x, u.y, hi.x, lo.x);
            split2(u.z, u.w, hi.y, lo.y);
            split2(v.x, v.y, hi.z, lo.z);
            split2(v.z, v.w, hi.w, lo.w);
            const uint32_t off = (uint32_t)r * 256u + (uint32_t)((c ^ (r & 7)) << 4);
            *(uint4*)(smc + SM_AHI + off) = hi;
            *(uint4*)(smc + SM_ALO + off) = lo;
        }
    }
    __syncthreads();

    // ---- warp tiling: wm in 0..1 (32 rows), wn in 0..3 (32 cols) ----
    const int lane = tid & 31;
    const int wid  = tid >> 5;
    const int wm = wid & 1;
    const int wn = wid >> 1;
    const int m0 = wm * 32;
    const int n0 = wn * 32;
    const int sub = lane >> 3, l8 = lane & 7;

    float acc[2][4][4];
    #pragma unroll
    for (int at = 0; at < 2; at++)
        #pragma unroll
        for (int nt = 0; nt < 4; nt++)
            #pragma unroll
            for (int q = 0; q < 4; q++) acc[at][nt][q] = 0.f;

    for (int ks = 0; ks < 8; ks++) {
        uint32_t ahi[2][4], alo[2][4], bhi[2][4], blo[2][4];
        #pragma unroll
        for (int at = 0; at < 2; at++) {
            const int ar  = m0 + at * 16 + (sub & 1) * 8 + l8;
            const int akc = ks * 2 + (sub >> 1);
            const uint32_t aoff = (uint32_t)ar * 256u + (uint32_t)((akc ^ (ar & 7)) << 4);
            ldmx4(ahi[at], sb + SM_AHI + aoff);
            ldmx4(alo[at], sb + SM_ALO + aoff);
        }
        #pragma unroll
        for (int bp = 0; bp < 2; bp++) {
            const int br  = n0 + bp * 16 + (sub >> 1) * 8 + l8;
            const int bkc = ks * 2 + (sub & 1);
            const uint32_t boff = (uint32_t)br * 256u + (uint32_t)((bkc ^ (br & 7)) << 4);
            ldmx4(bhi[bp], sb + SM_BHI + boff);
            ldmx4(blo[bp], sb + SM_BLO + boff);
        }
        #pragma unroll
        for (int at = 0; at < 2; at++) {
            #pragma unroll
            for (int nt = 0; nt < 4; nt++) {
                const int bp = nt >> 1, o = (nt & 1) * 2;
                mma_bf16(acc[at][nt], ahi[at], bhi[bp][o], bhi[bp][o + 1]);
                mma_bf16(acc[at][nt], ahi[at], blo[bp][o], blo[bp][o + 1]);
                mma_bf16(acc[at][nt], alo[at], bhi[bp][o], bhi[bp][o + 1]);
            }
        }
    }

    // ---- epilogue ----
    const bool hasMul = (mulSrc != nullptr);
    #pragma unroll
    for (int at = 0; at < 2; at++) {
        const int rloc = m0 + at * 16 + (lane >> 2);
        const int rA = rowBase + rloc;
        const int rB = rA + 8;
        float dA = 1.f, dB = 1.f;
        if (deg != nullptr) {
            if (rA < M) dA = (float)deg[rA];
            if (rB < M) dB = (float)deg[rB];
        }
        #pragma unroll
        for (int nt = 0; nt < 4; nt++) {
            const int col = n0 + nt * 8 + (lane & 3) * 2;
            const float2 b2 = *(const float2*)(bias + col);
            if (rA < M) {
                float v0 = acc[at][nt][0] + b2.x * dA;
                float v1 = acc[at][nt][1] + b2.y * dA;
                if (hasMul) {
                    float2 m = *(const float2*)(mulSrc + (size_t)rA * D + col);
                    v0 = fmaf(m.x, v0, m.x);
                    v1 = fmaf(m.y, v1, m.y);
                }
                *(float2*)(C + (size_t)rA * D + col) = make_float2(v0, v1);
            }
            if (rB < M) {
                float v0 = acc[at][nt][2] + b2.x * dB;
                float v1 = acc[at][nt][3] + b2.y * dB;
                if (hasMul) {
                    float2 m = *(const float2*)(mulSrc + (size_t)rB * D + col);
                    v0 = fmaf(m.x, v0, m.x);
                    v1 = fmaf(m.y, v1, m.y);
                }
                *(float2*)(C + (size_t)rB * D + col) = make_float2(v0, v1);
            }
        }
    }
}

// ---------------------------------------------------------------------------
// CSR build
// ---------------------------------------------------------------------------
__global__ void hist_kernel(const int* __restrict__ vidx, const int* __restrict__ eidx,
                            int* __restrict__ cnt, int nx, int E)
{
    int e = blockIdx.x * blockDim.x + threadIdx.x;
    if (e < E) {
        atomicAdd(&cnt[vidx[e]], 1);
        atomicAdd(&cnt[nx + eidx[e]], 1);
    }
}

__global__ void __launch_bounds__(1024)
offsets_kernel(const int* __restrict__ cnt, int* __restrict__ beg,
               int* __restrict__ cur, int* __restrict__ ctr,
               int nx, int nw, int nbx)
{
    const int isW = (blockIdx.x >= nbx) ? 1 : 0;
    const int blk = isW ? (blockIdx.x - nbx) : blockIdx.x;
    const int n   = isW ? nw : nx;
    const int off = isW ? nx : 0;

    const int t = threadIdx.x;
    const int i = blk * 1024 + t;
    int v = (i < n) ? cnt[off + i] : 0;

    const int lane = t & 31, wd = t >> 5;
    int s = v;
    #pragma unroll
    for (int o = 1; o < 32; o <<= 1) {
        int u = __shfl_up_sync(0xffffffffu, s, o);
        if (lane >= o) s += u;
    }
    __shared__ int wsum[32];
    __shared__ int base;
    if (lane == 31) wsum[wd] = s;
    __syncthreads();
    if (wd == 0) {
        int ws = wsum[lane];
        #pragma unroll
        for (int o = 1; o < 32; o <<= 1) {
            int u = __shfl_up_sync(0xffffffffu, ws, o);
            if (lane >= o) ws += u;
        }
        wsum[lane] = ws;
        if (lane == 31) base = atomicAdd(&ctr[isW], ws);
    }
    __syncthreads();
    int excl = base + s - v + (wd > 0 ? wsum[wd - 1] : 0);
    if (i < n) { beg[off + i] = excl; cur[off + i] = excl; }
}

__global__ void place_kernel(const int* __restrict__ vidx, const int* __restrict__ eidx,
                             int* __restrict__ cur, int* __restrict__ srcx,
                             int* __restrict__ srcw, int nx, int E)
{
    int e = blockIdx.x * blockDim.x + threadIdx.x;
    if (e < E) {
        int v = vidx[e], hw = eidx[e];
        int p1 = atomicAdd(&cur[v], 1);
        srcx[p1] = hw;
        int p2 = atomicAdd(&cur[nx + hw], 1);
        srcw[p2] = v;
    }
}

__global__ void zero_kernel(int* __restrict__ p, int n)
{
    int i = blockIdx.x * blockDim.x + threadIdx.x;
    if (i < n) p[i] = 0;
}

// ---------------------------------------------------------------------------
// Segment gather-reduce: warp per segment; lane = float4 chunk. 8-deep MLP.
// ---------------------------------------------------------------------------
__global__ void seg_reduce_kernel(const int* __restrict__ beg, const int* __restrict__ cnt,
                                  const int* __restrict__ lst,
                                  const float* __restrict__ src, const float* __restrict__ lin,
                                  float* __restrict__ out, int N)
{
    const int seg  = (blockIdx.x * blockDim.x + threadIdx.x) >> 5;
    const int lane = threadIdx.x & 31;
    if (seg >= N) return;
    int k = beg[seg];
    const int end = k + cnt[seg];
    const int j = lane * 4;
    float4 acc = make_float4(0.f, 0.f, 0.f, 0.f);

    for (; k + 7 < end; k += 8) {
        int si[8];
        #pragma unroll
        for (int q = 0; q < 8; q++) si[q] = __ldg(&lst[k + q]);
        float4 v[8];
        #pragma unroll
        for (int q = 0; q < 8; q++)
            v[q] = *(const float4*)(src + (size_t)si[q] * D + j);
        #pragma unroll
        for (int q = 0; q < 8; q++) {
            acc.x += v[q].x; acc.y += v[q].y; acc.z += v[q].z; acc.w += v[q].w;
        }
    }
    if (k + 3 < end) {
        int si[4];
        #pragma unroll
        for (int q = 0; q < 4; q++) si[q] = __ldg(&lst[k + q]);
        float4 v[4];
        #pragma unroll
        for (int q = 0; q < 4; q++)
            v[q] = *(const float4*)(src + (size_t)si[q] * D + j);
        #pragma unroll
        for (int q = 0; q < 4; q++) {
            acc.x += v[q].x; acc.y += v[q].y; acc.z += v[q].z; acc.w += v[q].w;
        }
        k += 4;
    }
    for (; k < end; k++) {
        int s0 = __ldg(&lst[k]);
        float4 v0 = *(const float4*)(src + (size_t)s0 * D + j);
        acc.x += v0.x; acc.y += v0.y; acc.z += v0.z; acc.w += v0.w;
    }

    float4 o;
    if (lin != nullptr) {
        float4 l = *(const float4*)(lin + (size_t)seg * D + j);
        o.x = fmaf(acc.x, l.x, l.x);
        o.y = fmaf(acc.y, l.y, l.y);
        o.z = fmaf(acc.z, l.z, l.z);
        o.w = fmaf(acc.w, l.w, l.w);
    } else {
        o = acc;
    }
    *(float4*)(out + (size_t)seg * D + j) = o;
}

extern "C" void kernel_launch(void* const* d_in, const int* in_sizes, int n_in,
                              void* d_out, int out_size)
{
    const float* x   = (const float*)d_in[0];
    const float* w   = (const float*)d_in[1];
    const float* Wx1 = (const float*)d_in[2];
    const float* bx1 = (const float*)d_in[3];
    const float* Ww1 = (const float*)d_in[4];
    const float* bw1 = (const float*)d_in[5];
    const float* Wx2 = (const float*)d_in[6];
    const float* bx2 = (const float*)d_in[7];
    const float* Ww2 = (const float*)d_in[8];
    const float* bw2 = (const float*)d_in[9];
    const int*   h   = (const int*)d_in[10];

    const int N_X = in_sizes[0] / D;
    const int N_W = in_sizes[1] / D;
    const int E   = in_sizes[10] / 2;
    const int* vidx = h;
    const int* eidx = h + E;

    float* out_w = (float*)d_out;
    float* out_x = (float*)d_out + (size_t)N_W * D;

    float *p_xv, *p_wv, *p_we, *p_s;
    int *p_cnt, *p_beg, *p_cur, *p_srcx, *p_srcw;
    cudaGetSymbolAddress((void**)&p_xv,   g_xv);
    cudaGetSymbolAddress((void**)&p_wv,   g_wv);
    cudaGetSymbolAddress((void**)&p_we,   g_we);
    cudaGetSymbolAddress((void**)&p_s,    g_s);
    cudaGetSymbolAddress((void**)&p_cnt,  g_cnt);
    cudaGetSymbolAddress((void**)&p_beg,  g_beg);
    cudaGetSymbolAddress((void**)&p_cur,  g_cur);
    cudaGetSymbolAddress((void**)&p_srcx, g_srcx);
    cudaGetSymbolAddress((void**)&p_srcw, g_srcw);
    int* p_ctr = p_cnt + MAX_NX + MAX_NW;

    cudaFuncSetAttribute(gemm_hmma_kernel,
                         cudaFuncAttributeMaxDynamicSharedMemorySize, SM_TOT);

    static cudaStream_t sA = nullptr, sB = nullptr;
    static cudaEvent_t e0 = nullptr, eA = nullptr, eA2 = nullptr, eB = nullptr, eS1 = nullptr;
    if (sA == nullptr) {
        cudaStreamCreateWithFlags(&sA, cudaStreamNonBlocking);
        cudaStreamCreateWithFlags(&sB, cudaStreamNonBlocking);
        cudaEventCreateWithFlags(&e0,  cudaEventDisableTiming);
        cudaEventCreateWithFlags(&eA,  cudaEventDisableTiming);
        cudaEventCreateWithFlags(&eA2, cudaEventDisableTiming);
        cudaEventCreateWithFlags(&eB,  cudaEventDisableTiming);
        cudaEventCreateWithFlags(&eS1, cudaEventDisableTiming);
    }

    const int gx  = (N_X + 63) / 64;
    const int gw  = (N_W + 63) / 64;
    const int nbx = (N_X + 1023) / 1024;
    const int nbw = (N_W + 1023) / 1024;
    const int ge  = (E + 255) / 256;

    // fork
    cudaEventRecord(e0, 0);
    cudaStreamWaitEvent(sA, e0, 0);
    cudaStreamWaitEvent(sB, e0, 0);

    // ---- stream B: CSR build (cnt all-zero on entry by invariant) ----
    hist_kernel<<<ge, 256, 0, sB>>>(vidx, eidx, p_cnt, N_X, E);
    offsets_kernel<<<nbx + nbw, 1024, 0, sB>>>(p_cnt, p_beg, p_cur, p_ctr, N_X, N_W, nbx);
    place_kernel<<<ge, 256, 0, sB>>>(vidx, eidx, p_cur, p_srcx, p_srcw, N_X, E);
    cudaEventRecord(eB, sB);

    // ---- stream A: weight precompute + GEMMs ----
    // mats: 0=Ww1, 1=Wx1, 2=Ww2, 3=Wx2
    conv_w_kernel<<<32, 256, 0, sA>>>(Ww1, Wx1, Ww2, Wx2);
    gemm_hmma_kernel<<<gw, 256, SM_TOT, sA>>>(w, 0, bw1, p_wv, N_W, nullptr, nullptr);
    gemm_hmma_kernel<<<gx, 256, SM_TOT, sA>>>(x, 1, bx1, p_xv, N_X, nullptr, nullptr);
    cudaEventRecord(eA, sA);

    // join for phase 1
    cudaStreamWaitEvent(0, eA, 0);
    cudaStreamWaitEvent(0, eB, 0);

    // ---- sr1: x_new = xv * (1 + segsum_v(wv)) ----
    seg_reduce_kernel<<<(N_X + 7) / 8, 256>>>(p_beg, p_cnt, p_srcx, p_wv, p_xv, out_x, N_X);
    cudaEventRecord(eS1, 0);

    // ---- we-GEMM on stream A (overlaps sr1) ----
    gemm_hmma_kernel<<<gw, 256, SM_TOT, sA>>>(w, 2, bw2, p_we, N_W, nullptr, nullptr);
    cudaEventRecord(eA2, sA);

    // ---- re-zero x-part of cnt (after sr1 consumed it) on stream B ----
    cudaStreamWaitEvent(sB, eS1, 0);
    zero_kernel<<<(N_X + 255) / 256, 256, 0, sB>>>(p_cnt, N_X);
    cudaEventRecord(eB, sB);

    // ---- phase 2: s = segsum_e(x_new); w_new = we*(1 + s@Wx2^T + deg*bx2) ----
    seg_reduce_kernel<<<(N_W + 7) / 8, 256>>>(p_beg + N_X, p_cnt + N_X, p_srcw,
                                              out_x, nullptr, p_s, N_W);
    cudaStreamWaitEvent(0, eA2, 0);
    gemm_hmma_kernel<<<gw, 256, SM_TOT>>>(p_s, 3, bx2, out_w, N_W, p_cnt + N_X, p_we);

    // ---- tail: restore zero-invariant for w-part of cnt + counters ----
    zero_kernel<<<(N_W + 2 + 255) / 256, 256>>>(p_cnt + N_X, N_W + 2);
    cudaStreamWaitEvent(0, eB, 0);
}